// round 7
// baseline (speedup 1.0000x reference)
#include <cuda_runtime.h>

#define TPB  256
#define PPT  4
#define TILE (TPB * PPT)   // 1024 points per block

typedef unsigned long long u64;

__device__ __forceinline__ u64 f2_pack(float lo, float hi) {
    u64 r; asm("mov.b64 %0,{%1,%2};" : "=l"(r) : "f"(lo), "f"(hi)); return r;
}
__device__ __forceinline__ u64 f2_add(u64 a, u64 b) {
    u64 r; asm("add.rn.f32x2 %0,%1,%2;" : "=l"(r) : "l"(a), "l"(b)); return r;
}
__device__ __forceinline__ u64 f2_mul(u64 a, u64 b) {
    u64 r; asm("mul.rn.f32x2 %0,%1,%2;" : "=l"(r) : "l"(a), "l"(b)); return r;
}
__device__ __forceinline__ float2 f2_unpack(u64 v) {
    float2 r; asm("mov.b64 {%0,%1},%2;" : "=f"(r.x), "=f"(r.y) : "l"(v)); return r;
}

// Record: 10 u64 pairs per cell (80 B, 16B-aligned for LDS.128 pair loads):
//  [0] (-ax,-ay)  [1] (-bx,-by)  [2] (-cx,-cy)
//  [3] (d0y,d0x)  [4] (d1y,d1x)  [5] (d2y,d2x)
//  [6] (-ocx,-ocy) [7] (-ecx,-ecy) [8] (1/erx,1/ery) [9] (r2,0)
// Negated centers: add.rn.f32x2(P, -c) == exact (px-cx, py-cy).
__device__ __forceinline__ int shade_cell(const u64* __restrict__ recu,
                                          int cc, u64 P, int best, bool valid)
{
    const ulonglong2* R = (const ulonglong2*)(recu + cc * 10);
    ulonglong2 L01 = R[0];
    ulonglong2 L23 = R[1];
    ulonglong2 L45 = R[2];
    ulonglong2 L67 = R[3];
    ulonglong2 L89 = R[4];

    // Triangle — identical rounding to reference:
    // e = (px-vx)*dY - (py-vy)*dX, each op rn, no fma contraction.
    u64 pa = f2_add(P, L01.x);
    u64 pb = f2_add(P, L01.y);
    u64 pc = f2_add(P, L23.x);
    float2 m0 = f2_unpack(f2_mul(pa, L23.y));
    float2 m1 = f2_unpack(f2_mul(pb, L45.x));
    float2 m2 = f2_unpack(f2_mul(pc, L45.y));
    float e0 = __fsub_rn(m0.x, m0.y);
    float e1 = __fsub_rn(m1.x, m1.y);
    float e2 = __fsub_rn(m2.x, m2.y);
    float emin = fminf(fminf(e0, e1), e2);
    float emax = fmaxf(fmaxf(e0, e1), e2);
    bool tri_in = (emin >= 0.0f) || (emax <= 0.0f);

    // Circle
    u64 dc = f2_add(P, L67.x);
    float2 q = f2_unpack(f2_mul(dc, dc));
    float2 rp = f2_unpack(L89.y);
    bool circ_in = __fadd_rn(q.x, q.y) <= rp.x;

    // Ellipse (reciprocal precompute, validated rel_err == 0.0)
    u64 de = f2_add(P, L67.y);
    u64 s = f2_mul(de, L89.x);
    float2 s2 = f2_unpack(f2_mul(s, s));
    bool ell_in = __fadd_rn(s2.x, s2.y) <= 1.0f;

    int c3 = cc * 3;
    int cb = tri_in  ? c3     : -1;
    cb     = circ_in ? c3 + 1 : cb;
    cb     = ell_in  ? c3 + 2 : cb;
    cb     = valid   ? cb     : -1;
    return best > cb ? best : cb;
}

__global__ __launch_bounds__(TPB)
void vg_kernel(const float* __restrict__ x, const float* __restrict__ p,
               float* __restrict__ out, int n)
{
    __shared__ u64  recu[25 * 10];
    __shared__ float colors[76 * 3];       // slot 0 = black
    __shared__ float2 sp[TILE];            // (cell,quadrant)-sorted points
    __shared__ unsigned int stmp[TILE];    // key | rank<<8 | extra<<18
    __shared__ unsigned int sinfo[TILE];   // orig | extra<<10
    __shared__ unsigned char sbest[TILE];  // winner+1 per ORIGINAL point
    __shared__ int hist[225];
    __shared__ int off[225];
    __shared__ int wsum[8];

    const int tid = threadIdx.x;

    if (tid < 25) {
        const float* q = p + tid * 28;
        float ax = q[1], ay = q[2], bx = q[3], by = q[4], cx = q[5], cy = q[6];
        float* f = (float*)(recu + tid * 10);
        f[0]  = -ax;  f[1]  = -ay;
        f[2]  = -bx;  f[3]  = -by;
        f[4]  = -cx;  f[5]  = -cy;
        f[6]  = __fsub_rn(by, ay); f[7]  = __fsub_rn(bx, ax);
        f[8]  = __fsub_rn(cy, by); f[9]  = __fsub_rn(cx, bx);
        f[10] = __fsub_rn(ay, cy); f[11] = __fsub_rn(ax, cx);
        f[12] = -q[12]; f[13] = -q[13];       // -ocx,-ocy
        f[14] = -q[20]; f[15] = -q[21];       // -ecx,-ecy
        f[16] = 1.0f / q[22]; f[17] = 1.0f / q[23];
        f[18] = __fmul_rn(q[14], q[14]); f[19] = 0.0f;
    }
    for (int idx = tid; idx < 228; idx += TPB) {
        if (idx < 3) colors[idx] = 0.0f;
        else {
            int s = (idx - 3) / 3, k = (idx - 3) % 3;
            int c = s / 3, t = s % 3;
            int o = (t == 0) ? (8 + k) : ((t == 1) ? (16 + k) : (25 + k));
            colors[idx] = p[c * 28 + o];
        }
    }
    if (tid < 225) hist[tid] = 0;
    __syncthreads();

    const int base = blockIdx.x * TILE;

    // ---- Phase 1: load points, classify, histogram ----
    float2 pts[PPT];
#pragma unroll
    for (int k = 0; k < PPT; k++) {
        int li = k * TPB + tid;
        int gi = base + li;
        float2 pt = (gi < n) ? ((const float2*)x)[gi] : make_float2(0.5f, 0.5f);
        pts[k] = pt;
        float gx = pt.x * 5.0f, gy = pt.y * 5.0f;
        int ci = (int)gx; ci = ci > 4 ? 4 : (ci < 0 ? 0 : ci);
        int cj = (int)gy; cj = cj > 4 ? 4 : (cj < 0 ? 0 : cj);
        float fx = gx - (float)ci;
        float fy = gy - (float)cj;
        // shapes extend at most 0.4 cell-widths outside their cell;
        // 0.41/0.59 thresholds leave 0.002-abs margin >> f32 rounding
        int dxn = (fx <= 0.41f) ? -1 : ((fx >= 0.59f) ? 1 : 0);
        int dyn = (fy <= 0.41f) ? -1 : ((fy >= 0.59f) ? 1 : 0);
        int i2 = ci + dxn, j2 = cj + dyn;
        unsigned vx = (dxn != 0) && ((unsigned)i2 <= 4u);
        unsigned vy = (dyn != 0) && ((unsigned)j2 <= 4u);
        int cc = ci * 5 + cj;
        int key = cc * 9 + (dxn + 1) * 3 + (dyn + 1);
        unsigned extra = (unsigned)cc | ((unsigned)(dxn + 1) << 5) |
                         ((unsigned)(dyn + 1) << 7) | (vx << 9) | (vy << 10);
        int rank = atomicAdd(&hist[key], 1);
        stmp[li] = (unsigned)key | ((unsigned)rank << 8) | (extra << 18);
    }
    __syncthreads();

    // ---- Phase 2: exclusive scan of 225 bins (two-level shuffle scan) ----
    {
        int v = (tid < 225) ? hist[tid] : 0;
        int s = v;
#pragma unroll
        for (int d = 1; d < 32; d <<= 1) {
            int t = __shfl_up_sync(0xffffffff, s, d);
            if ((tid & 31) >= d) s += t;
        }
        if ((tid & 31) == 31) wsum[tid >> 5] = s;
        __syncthreads();
        if (tid < 8) {
            int w = wsum[tid];
            int sw = w;
#pragma unroll
            for (int d = 1; d < 8; d <<= 1) {
                int t = __shfl_up_sync(0xff, sw, d);
                if (tid >= d) sw += t;
            }
            wsum[tid] = sw - w;
        }
        __syncthreads();
        if (tid < 225) off[tid] = (s - v) + wsum[tid >> 5];
    }
    __syncthreads();

    // ---- Phase 3: scatter into (cell,quadrant)-sorted order ----
#pragma unroll
    for (int k = 0; k < PPT; k++) {
        int li = k * TPB + tid;
        unsigned m = stmp[li];
        int pos = off[m & 255] + (int)((m >> 8) & 1023);
        sp[pos]    = pts[k];
        sinfo[pos] = (unsigned)li | ((m >> 18) << 10);
    }
    __syncthreads();

    // ---- Phase 4: uniform 4-cell shading (select-masked, no branches) ----
#pragma unroll 1
    for (int k = 0; k < PPT; k++) {
        int li = k * TPB + tid;
        float2 pt = sp[li];
        unsigned m = sinfo[li];
        int orig = m & 1023;
        int cc   = (m >> 10) & 31;
        int dxn  = (int)((m >> 15) & 3) - 1;
        int dyn  = (int)((m >> 17) & 3) - 1;
        bool vx  = (m >> 19) & 1;
        bool vy  = (m >> 20) & 1;

        u64 P = f2_pack(pt.x, pt.y);
        int ccx  = vx ? cc + dxn * 5 : cc;
        int ccy  = vy ? cc + dyn     : cc;
        int ccxy = ccx + (ccy - cc);

        int best = -1;
        best = shade_cell(recu, cc,   P, best, true);
        best = shade_cell(recu, ccx,  P, best, vx);
        best = shade_cell(recu, ccy,  P, best, vy);
        best = shade_cell(recu, ccxy, P, best, vx && vy);

        sbest[orig] = (unsigned char)(best + 1);
    }
    __syncthreads();

    // ---- Phase 5: output in original order ----
#pragma unroll
    for (int k = 0; k < PPT; k++) {
        int li = k * TPB + tid;
        int gi = base + li;
        if (gi < n) {
            int cb = (int)sbest[li] * 3;
            out[gi * 3 + 0] = colors[cb + 0];
            out[gi * 3 + 1] = colors[cb + 1];
            out[gi * 3 + 2] = colors[cb + 2];
        }
    }
}

extern "C" void kernel_launch(void* const* d_in, const int* in_sizes, int n_in,
                              void* d_out, int out_size)
{
    // Identify inputs robustly: x has 2*N elements, p has 700
    int xi = 0, pi = 1;
    if (n_in >= 2 && in_sizes[0] < in_sizes[1]) { xi = 1; pi = 0; }
    const float* x = (const float*)d_in[xi];
    const float* p = (const float*)d_in[pi];
    float* out = (float*)d_out;

    int n = in_sizes[xi] / 2;
    int blocks = (n + TILE - 1) / TILE;
    vg_kernel<<<blocks, TPB>>>(x, p, out, n);
}